// round 6
// baseline (speedup 1.0000x reference)
#include <cuda_runtime.h>
#include <cuda_fp16.h>
#include <cstdint>

// Problem constants
#define N_ROWS 16384
#define KNB    25
#define DIM    512
#define ODIM   1024

// GEMM tile
#define BM 128
#define BN 64
#define BK 32
#define SROW 40                      // halves per smem row (80B) -> conflict-free ldmatrix
#define NKT (DIM / BK)               // 16
#define STAGE_A (BM * SROW)          // 5120 halves
#define STAGE_B (BN * SROW)          // 2560 halves
#define STAGE_HALVES (STAGE_A + STAGE_B)
#define SMEM_BYTES (2 * STAGE_HALVES * 2)   // 30720 B (2 stages)

// Work decomposition
#define W_UNITS 32                   // 4 x (64x64) transpose tiles each
#define MEAN_UNITS 4096              // 4 rows each
#define UNITS_TOTAL (W_UNITS + MEAN_UNITS)
#define UNITS_PER_MB 32              // 128 rows / 4
#define WINDOW 768                   // ~24 m-blocks of concurrent mean work
#define GEMM_ITEMS 2048              // mb = g>>4, nb = g&15 (16 n-tiles of 64)
#define GRID_CTAS 1036

// Scratch + control (device globals — no allocation allowed)
__device__ __half g_A [N_ROWS * DIM];
__device__ __half g_WT[ODIM  * DIM];
__device__ int g_unit_next, g_gemm_next, g_units_done, g_wcount;
__device__ int g_mb_count[128];

// ---------------------------------------------------------------------------
__global__ void __launch_bounds__(256) zero_kernel()
{
    int t = threadIdx.x;
    if (t < 128) g_mb_count[t] = 0;
    if (t == 128) g_unit_next = 0;
    if (t == 129) g_gemm_next = 0;
    if (t == 130) g_units_done = 0;
    if (t == 131) g_wcount = 0;
}

// ---------------------------------------------------------------------------
// helpers
// ---------------------------------------------------------------------------
__device__ __forceinline__ uint32_t smem_addr32(const void* p) {
    return (uint32_t)__cvta_generic_to_shared(p);
}
__device__ __forceinline__ void ldmatrix_x4(uint32_t& r0, uint32_t& r1,
                                            uint32_t& r2, uint32_t& r3, uint32_t addr) {
    asm volatile("ldmatrix.sync.aligned.m8n8.x4.shared.b16 {%0,%1,%2,%3}, [%4];"
                 : "=r"(r0), "=r"(r1), "=r"(r2), "=r"(r3) : "r"(addr));
}
__device__ __forceinline__ void mma16816(float* c, const uint32_t* a, const uint32_t* b) {
    asm volatile(
        "mma.sync.aligned.m16n8k16.row.col.f32.f16.f16.f32 "
        "{%0,%1,%2,%3}, {%4,%5,%6,%7}, {%8,%9}, {%0,%1,%2,%3};"
        : "+f"(c[0]), "+f"(c[1]), "+f"(c[2]), "+f"(c[3])
        : "r"(a[0]), "r"(a[1]), "r"(a[2]), "r"(a[3]), "r"(b[0]), "r"(b[1]));
}
__device__ __forceinline__ void cp_async16(uint32_t dst, const void* src) {
    asm volatile("cp.async.cg.shared.global [%0], [%1], 16;" :: "r"(dst), "l"(src));
}

// ---------------------------------------------------------------------------
// W transpose unit: 4 tiles of 64x64, staged in dyn smem (pad 65)
// ---------------------------------------------------------------------------
__device__ void do_w_unit(int u, const float* __restrict__ W, __half* stage, int tid)
{
    #pragma unroll 1
    for (int j = 0; j < 4; j++) {
        int i = u * 4 + j;
        int bk = i & 7, bo = i >> 3;
        #pragma unroll
        for (int p = 0; p < 16; p++) {
            int idx = tid + p * 256;
            int kk = idx >> 6, oo = idx & 63;
            stage[kk * 65 + oo] =
                __float2half_rn(W[(size_t)(bk * 64 + kk) * ODIM + bo * 64 + oo]);
        }
        __syncthreads();
        #pragma unroll
        for (int p = 0; p < 16; p++) {
            int idx = tid + p * 256;
            int oo = idx >> 6, kk = idx & 63;
            g_WT[(size_t)(bo * 64 + oo) * DIM + bk * 64 + kk] = stage[kk * 65 + oo];
        }
        __syncthreads();
    }
}

// ---------------------------------------------------------------------------
// Mean unit: 4 rows; 256 threads = 2 rows per pass, 2 passes
// ---------------------------------------------------------------------------
__device__ void do_mean_unit(int m, const float* __restrict__ self_vecs,
                             const float* __restrict__ neigh, int tid)
{
    int lane = tid & 127;
    #pragma unroll
    for (int p = 0; p < 2; p++) {
        int r = m * 4 + p * 2 + (tid >> 7);
        const float4* sv = (const float4*)self_vecs + (size_t)r * 128;
        const float4* nv = (const float4*)neigh + ((size_t)r * KNB) * 128;
        float4 acc = sv[lane];
        #pragma unroll
        for (int k = 0; k < KNB; k++) {
            float4 v = nv[(size_t)k * 128 + lane];
            acc.x += v.x; acc.y += v.y; acc.z += v.z; acc.w += v.w;
        }
        const float inv = 1.0f / (float)(KNB + 1);
        acc.x *= inv; acc.y *= inv; acc.z *= inv; acc.w *= inv;
        __half2* o = (__half2*)g_A + (size_t)r * 256;
        o[lane * 2 + 0] = __floats2half2_rn(acc.x, acc.y);
        o[lane * 2 + 1] = __floats2half2_rn(acc.z, acc.w);
    }
}

// ---------------------------------------------------------------------------
// GEMM item: 128x64 output tile, 2-stage cp.async, fp16 mma, bias+relu
// 8 warps: warp_m = wid&3 (32 rows), warp_n = wid>>2 (32 cols)
// ---------------------------------------------------------------------------
__device__ void do_gemm(int mb, int nb, const float* __restrict__ bias,
                        float* __restrict__ out, __half* dyn, int tid)
{
    int wid = tid >> 5;
    int lane = tid & 31;
    int warp_m = wid & 3;
    int warp_n = wid >> 2;
    int m0 = mb * BM;
    int n0 = nb * BN;

    const __half* gA = g_A  + (size_t)m0 * DIM;
    const __half* gB = g_WT + (size_t)n0 * DIM;

    uint32_t base = smem_addr32(dyn);
    uint32_t sAb[2] = { base, base + STAGE_HALVES * 2 };
    uint32_t sBb[2] = { base + STAGE_A * 2, base + STAGE_HALVES * 2 + STAGE_A * 2 };

    // cp.async coords: A: 2 chunks/thread; B: 1 chunk/thread
    int a_r0 = tid >> 2,          a_c0 = (tid & 3) * 8;
    int a_r1 = (tid + 256) >> 2,  a_c1 = ((tid + 256) & 3) * 8;
    int b_r  = tid >> 2,          b_c  = (tid & 3) * 8;   // rows 0..63

    float acc[2][4][4];
    #pragma unroll
    for (int i = 0; i < 2; i++)
        #pragma unroll
        for (int j = 0; j < 4; j++)
            #pragma unroll
            for (int v = 0; v < 4; v++) acc[i][j][v] = 0.0f;

    // ldmatrix coords
    int a_row = warp_m * 32 + (lane & 15);
    int a_colb = ((lane >> 4) << 3);
    int quad = lane >> 3;
    int b_row_off = ((quad >> 1) << 3) + (lane & 7);
    int b_colb = ((quad & 1) << 3);

    // prologue: stage 0
    cp_async16(sAb[0] + (a_r0 * SROW + a_c0) * 2, gA + (size_t)a_r0 * DIM + a_c0);
    cp_async16(sAb[0] + (a_r1 * SROW + a_c1) * 2, gA + (size_t)a_r1 * DIM + a_c1);
    cp_async16(sBb[0] + (b_r  * SROW + b_c ) * 2, gB + (size_t)b_r  * DIM + b_c );
    asm volatile("cp.async.commit_group;");

    #pragma unroll 2
    for (int kt = 0; kt < NKT; kt++) {
        if (kt + 1 < NKT) {
            int s = (kt + 1) & 1;
            int kb = (kt + 1) * BK;
            cp_async16(sAb[s] + (a_r0 * SROW + a_c0) * 2, gA + (size_t)a_r0 * DIM + kb + a_c0);
            cp_async16(sAb[s] + (a_r1 * SROW + a_c1) * 2, gA + (size_t)a_r1 * DIM + kb + a_c1);
            cp_async16(sBb[s] + (b_r  * SROW + b_c ) * 2, gB + (size_t)b_r  * DIM + kb + b_c );
            asm volatile("cp.async.commit_group;");
            asm volatile("cp.async.wait_group 1;");
        } else {
            asm volatile("cp.async.wait_group 0;");
        }
        __syncthreads();

        int s = kt & 1;
        #pragma unroll
        for (int ks = 0; ks < 2; ks++) {
            uint32_t af[2][4];
            #pragma unroll
            for (int mt = 0; mt < 2; mt++) {
                uint32_t addr = sAb[s] + ((a_row + mt * 16) * SROW + ks * 16 + a_colb) * 2;
                ldmatrix_x4(af[mt][0], af[mt][1], af[mt][2], af[mt][3], addr);
            }
            uint32_t bf[4][2];
            #pragma unroll
            for (int ntp = 0; ntp < 2; ntp++) {
                uint32_t r0, r1, r2, r3;
                uint32_t addr = sBb[s] +
                    ((warp_n * 32 + ntp * 16 + b_row_off) * SROW + ks * 16 + b_colb) * 2;
                ldmatrix_x4(r0, r1, r2, r3, addr);
                bf[ntp * 2 + 0][0] = r0; bf[ntp * 2 + 0][1] = r1;
                bf[ntp * 2 + 1][0] = r2; bf[ntp * 2 + 1][1] = r3;
            }
            #pragma unroll
            for (int mt = 0; mt < 2; mt++)
                #pragma unroll
                for (int nt = 0; nt < 4; nt++)
                    mma16816(acc[mt][nt], af[mt], bf[nt]);
        }
        __syncthreads();
    }

    // epilogue: bias + relu, direct float2 stores
    #pragma unroll
    for (int nt = 0; nt < 4; nt++) {
        int col = n0 + warp_n * 32 + nt * 8 + ((lane & 3) << 1);
        float b0 = bias[col], b1 = bias[col + 1];
        #pragma unroll
        for (int mt = 0; mt < 2; mt++) {
            int row = m0 + warp_m * 32 + mt * 16 + (lane >> 2);
            float2 v0, v1;
            v0.x = fmaxf(acc[mt][nt][0] + b0, 0.0f);
            v0.y = fmaxf(acc[mt][nt][1] + b1, 0.0f);
            v1.x = fmaxf(acc[mt][nt][2] + b0, 0.0f);
            v1.y = fmaxf(acc[mt][nt][3] + b1, 0.0f);
            *(float2*)(out + (size_t)row * ODIM + col) = v0;
            *(float2*)(out + (size_t)(row + 8) * ODIM + col) = v1;
        }
    }
}

// ---------------------------------------------------------------------------
// Fused persistent kernel: work-stealing mean/W producers + GEMM consumers
// ---------------------------------------------------------------------------
__global__ void __launch_bounds__(256, 7) fused_kernel(
    const float* __restrict__ self_vecs, const float* __restrict__ neigh,
    const float* __restrict__ W, const float* __restrict__ bias,
    float* __restrict__ out)
{
    extern __shared__ __half dyn[];
    __shared__ int s_b;
    int tid = threadIdx.x;

    for (;;) {
        // claim next gemm item
        __syncthreads();
        if (tid == 0) s_b = atomicAdd(&g_gemm_next, 1);
        __syncthreads();
        int g = s_b;
        if (g >= GEMM_ITEMS) return;          // uniform per CTA
        int mb = g >> 4;
        int nb = g & 15;

        // wait until prerequisites ready; do producer work meanwhile
        for (;;) {
            __syncthreads();
            if (tid == 0) {
                bool ready = (atomicAdd(&g_wcount, 0) == W_UNITS) &&
                             (atomicAdd(&g_mb_count[mb], 0) == UNITS_PER_MB);
                s_b = ready ? -1 : atomicAdd(&g_unit_next, 1);
            }
            __syncthreads();
            int u = s_b;
            if (u < 0) break;                  // ready -> go do gemm
            if (u < W_UNITS) {
                do_w_unit(u, W, dyn, tid);
                __syncthreads();
                if (tid == 0) { __threadfence(); atomicAdd(&g_wcount, 1); }
            } else if (u < UNITS_TOTAL) {
                int m = u - W_UNITS;
                if (tid == 0) {
                    // sliding window: keep mean progress ordered/progressive
                    while (atomicAdd(&g_units_done, 0) + WINDOW <= m) __nanosleep(256);
                }
                __syncthreads();
                do_mean_unit(m, self_vecs, neigh, tid);
                __syncthreads();
                if (tid == 0) {
                    __threadfence();
                    atomicAdd(&g_units_done, 1);
                    atomicAdd(&g_mb_count[m >> 5], 1);
                }
            } else {
                if (tid == 0) __nanosleep(512);   // no producer work left; poll
            }
        }
        __threadfence();                       // acquire side before reading g_A/g_WT
        do_gemm(mb, nb, bias, out, dyn, tid);
    }
}

// ---------------------------------------------------------------------------
// Launch
// ---------------------------------------------------------------------------
extern "C" void kernel_launch(void* const* d_in, const int* in_sizes, int n_in,
                              void* d_out, int out_size)
{
    const float* self_vecs = (const float*)d_in[0];   // [16384, 512]
    const float* neigh     = (const float*)d_in[1];   // [16384, 25, 512]
    // d_in[2] = temperature (unused by reference)
    const float* W         = (const float*)d_in[3];   // [512, 1024]
    const float* b         = (const float*)d_in[4];   // [1024]
    float* out = (float*)d_out;                       // [16384, 1024]

    cudaFuncSetAttribute(fused_kernel, cudaFuncAttributePreferredSharedMemoryCarveout, 100);

    zero_kernel<<<1, 256>>>();
    fused_kernel<<<GRID_CTAS, 256, SMEM_BYTES>>>(self_vecs, neigh, W, b, out);
}

// round 7
// speedup vs baseline: 2.9912x; 2.9912x over previous
#include <cuda_runtime.h>
#include <cuda_fp16.h>
#include <cstdint>

// Problem constants
#define N_ROWS 16384
#define KNB    25
#define DIM    512
#define ODIM   1024

// GEMM tile
#define BM 128
#define BN 64
#define BK 32
#define SROW 40                      // halves per smem row (80B) -> conflict-free ldmatrix
#define NKT (DIM / BK)               // 16
#define STAGE_A (BM * SROW)          // 5120 halves
#define STAGE_B (BN * SROW)          // 2560 halves
#define STAGE_HALVES (STAGE_A + STAGE_B)
#define SMEM_BYTES (2 * STAGE_HALVES * 2)   // 30720 B (2 stages)

// Work decomposition
#define W_UNITS 32                   // 4 x (64x64) transpose tiles each
#define MEAN_UNITS 2048              // 8 rows each
#define UNITS_TOTAL (W_UNITS + MEAN_UNITS)
#define UNITS_PER_MB 16              // 128 rows / 8
#define GEMM_ITEMS 2048              // mb = g>>4 (128 x 128 rows), nb = g&15 (16 x 64 cols)
#define GRID_CTAS 296                // 2 CTAs/SM x 148 SMs, all resident

// Scratch + control (device globals — no allocation allowed)
__device__ __half g_A [N_ROWS * DIM];
__device__ __half g_WT[ODIM  * DIM];
__device__ int g_unit_next, g_gemm_next, g_wcount;
__device__ int g_mb_count[128];

// ---------------------------------------------------------------------------
__global__ void __launch_bounds__(256) zero_kernel()
{
    int t = threadIdx.x;
    if (t < 128) g_mb_count[t] = 0;
    if (t == 128) g_unit_next = 0;
    if (t == 129) g_gemm_next = 0;
    if (t == 130) g_wcount = 0;
}

// ---------------------------------------------------------------------------
// helpers
// ---------------------------------------------------------------------------
__device__ __forceinline__ uint32_t smem_addr32(const void* p) {
    return (uint32_t)__cvta_generic_to_shared(p);
}
__device__ __forceinline__ void ldmatrix_x4(uint32_t& r0, uint32_t& r1,
                                            uint32_t& r2, uint32_t& r3, uint32_t addr) {
    asm volatile("ldmatrix.sync.aligned.m8n8.x4.shared.b16 {%0,%1,%2,%3}, [%4];"
                 : "=r"(r0), "=r"(r1), "=r"(r2), "=r"(r3) : "r"(addr));
}
__device__ __forceinline__ void mma16816(float* c, const uint32_t* a, const uint32_t* b) {
    asm volatile(
        "mma.sync.aligned.m16n8k16.row.col.f32.f16.f16.f32 "
        "{%0,%1,%2,%3}, {%4,%5,%6,%7}, {%8,%9}, {%0,%1,%2,%3};"
        : "+f"(c[0]), "+f"(c[1]), "+f"(c[2]), "+f"(c[3])
        : "r"(a[0]), "r"(a[1]), "r"(a[2]), "r"(a[3]), "r"(b[0]), "r"(b[1]));
}
__device__ __forceinline__ void cp_async16(uint32_t dst, const void* src) {
    asm volatile("cp.async.cg.shared.global [%0], [%1], 16;" :: "r"(dst), "l"(src));
}

// ---------------------------------------------------------------------------
// W transpose unit: 4 tiles of 64x64, staged in dyn smem (pad 65)
// ---------------------------------------------------------------------------
__device__ void do_w_unit(int u, const float* __restrict__ W, __half* stage, int tid)
{
    #pragma unroll 1
    for (int j = 0; j < 4; j++) {
        int i = u * 4 + j;
        int bk = i & 7, bo = i >> 3;
        #pragma unroll
        for (int p = 0; p < 16; p++) {
            int idx = tid + p * 256;
            int kk = idx >> 6, oo = idx & 63;
            stage[kk * 65 + oo] =
                __float2half_rn(W[(size_t)(bk * 64 + kk) * ODIM + bo * 64 + oo]);
        }
        __syncthreads();
        #pragma unroll
        for (int p = 0; p < 16; p++) {
            int idx = tid + p * 256;
            int oo = idx >> 6, kk = idx & 63;
            g_WT[(size_t)(bo * 64 + oo) * DIM + bk * 64 + kk] = stage[kk * 65 + oo];
        }
        __syncthreads();
    }
}

// ---------------------------------------------------------------------------
// Mean unit: 8 rows; 256 threads = 2 rows per pass, 4 passes
// ---------------------------------------------------------------------------
__device__ void do_mean_unit(int m, const float* __restrict__ self_vecs,
                             const float* __restrict__ neigh, int tid)
{
    int lane = tid & 127;
    #pragma unroll
    for (int p = 0; p < 4; p++) {
        int r = m * 8 + p * 2 + (tid >> 7);
        const float4* sv = (const float4*)self_vecs + (size_t)r * 128;
        const float4* nv = (const float4*)neigh + ((size_t)r * KNB) * 128;
        float4 acc = sv[lane];
        #pragma unroll
        for (int k = 0; k < KNB; k++) {
            float4 v = nv[(size_t)k * 128 + lane];
            acc.x += v.x; acc.y += v.y; acc.z += v.z; acc.w += v.w;
        }
        const float inv = 1.0f / (float)(KNB + 1);
        acc.x *= inv; acc.y *= inv; acc.z *= inv; acc.w *= inv;
        __half2* o = (__half2*)g_A + (size_t)r * 256;
        o[lane * 2 + 0] = __floats2half2_rn(acc.x, acc.y);
        o[lane * 2 + 1] = __floats2half2_rn(acc.z, acc.w);
    }
}

// ---------------------------------------------------------------------------
// GEMM item: 128x64 output tile, 2-stage cp.async, fp16 mma, bias+relu
// ---------------------------------------------------------------------------
__device__ void do_gemm(int mb, int nb, const float* __restrict__ bias,
                        float* __restrict__ out, __half* dyn, int tid)
{
    int wid = tid >> 5;
    int lane = tid & 31;
    int warp_m = wid & 3;
    int warp_n = wid >> 2;
    int m0 = mb * BM;
    int n0 = nb * BN;

    const __half* gA = g_A  + (size_t)m0 * DIM;
    const __half* gB = g_WT + (size_t)n0 * DIM;

    uint32_t base = smem_addr32(dyn);
    uint32_t sAb[2] = { base, base + STAGE_HALVES * 2 };
    uint32_t sBb[2] = { base + STAGE_A * 2, base + STAGE_HALVES * 2 + STAGE_A * 2 };

    int a_r0 = tid >> 2,          a_c0 = (tid & 3) * 8;
    int a_r1 = (tid + 256) >> 2,  a_c1 = ((tid + 256) & 3) * 8;
    int b_r  = tid >> 2,          b_c  = (tid & 3) * 8;

    float acc[2][4][4];
    #pragma unroll
    for (int i = 0; i < 2; i++)
        #pragma unroll
        for (int j = 0; j < 4; j++)
            #pragma unroll
            for (int v = 0; v < 4; v++) acc[i][j][v] = 0.0f;

    int a_row = warp_m * 32 + (lane & 15);
    int a_colb = ((lane >> 4) << 3);
    int quad = lane >> 3;
    int b_row_off = ((quad >> 1) << 3) + (lane & 7);
    int b_colb = ((quad & 1) << 3);

    cp_async16(sAb[0] + (a_r0 * SROW + a_c0) * 2, gA + (size_t)a_r0 * DIM + a_c0);
    cp_async16(sAb[0] + (a_r1 * SROW + a_c1) * 2, gA + (size_t)a_r1 * DIM + a_c1);
    cp_async16(sBb[0] + (b_r  * SROW + b_c ) * 2, gB + (size_t)b_r  * DIM + b_c );
    asm volatile("cp.async.commit_group;");

    #pragma unroll 2
    for (int kt = 0; kt < NKT; kt++) {
        if (kt + 1 < NKT) {
            int s = (kt + 1) & 1;
            int kb = (kt + 1) * BK;
            cp_async16(sAb[s] + (a_r0 * SROW + a_c0) * 2, gA + (size_t)a_r0 * DIM + kb + a_c0);
            cp_async16(sAb[s] + (a_r1 * SROW + a_c1) * 2, gA + (size_t)a_r1 * DIM + kb + a_c1);
            cp_async16(sBb[s] + (b_r  * SROW + b_c ) * 2, gB + (size_t)b_r  * DIM + kb + b_c );
            asm volatile("cp.async.commit_group;");
            asm volatile("cp.async.wait_group 1;");
        } else {
            asm volatile("cp.async.wait_group 0;");
        }
        __syncthreads();

        int s = kt & 1;
        #pragma unroll
        for (int ks = 0; ks < 2; ks++) {
            uint32_t af[2][4];
            #pragma unroll
            for (int mt = 0; mt < 2; mt++) {
                uint32_t addr = sAb[s] + ((a_row + mt * 16) * SROW + ks * 16 + a_colb) * 2;
                ldmatrix_x4(af[mt][0], af[mt][1], af[mt][2], af[mt][3], addr);
            }
            uint32_t bf[4][2];
            #pragma unroll
            for (int ntp = 0; ntp < 2; ntp++) {
                uint32_t r0, r1, r2, r3;
                uint32_t addr = sBb[s] +
                    ((warp_n * 32 + ntp * 16 + b_row_off) * SROW + ks * 16 + b_colb) * 2;
                ldmatrix_x4(r0, r1, r2, r3, addr);
                bf[ntp * 2 + 0][0] = r0; bf[ntp * 2 + 0][1] = r1;
                bf[ntp * 2 + 1][0] = r2; bf[ntp * 2 + 1][1] = r3;
            }
            #pragma unroll
            for (int mt = 0; mt < 2; mt++)
                #pragma unroll
                for (int nt = 0; nt < 4; nt++)
                    mma16816(acc[mt][nt], af[mt], bf[nt]);
        }
        __syncthreads();
    }

    #pragma unroll
    for (int nt = 0; nt < 4; nt++) {
        int col = n0 + warp_n * 32 + nt * 8 + ((lane & 3) << 1);
        float b0 = bias[col], b1 = bias[col + 1];
        #pragma unroll
        for (int mt = 0; mt < 2; mt++) {
            int row = m0 + warp_m * 32 + mt * 16 + (lane >> 2);
            float2 v0, v1;
            v0.x = fmaxf(acc[mt][nt][0] + b0, 0.0f);
            v0.y = fmaxf(acc[mt][nt][1] + b1, 0.0f);
            v1.x = fmaxf(acc[mt][nt][2] + b0, 0.0f);
            v1.y = fmaxf(acc[mt][nt][3] + b1, 0.0f);
            *(float2*)(out + (size_t)row * ODIM + col) = v0;
            *(float2*)(out + (size_t)(row + 8) * ODIM + col) = v1;
        }
    }
}

// ---------------------------------------------------------------------------
// Fused persistent kernel: claim GEMM item; help with mean/W units until ready
// ---------------------------------------------------------------------------
__global__ void __launch_bounds__(256, 2) fused_kernel(
    const float* __restrict__ self_vecs, const float* __restrict__ neigh,
    const float* __restrict__ W, const float* __restrict__ bias,
    float* __restrict__ out)
{
    extern __shared__ __half dyn[];
    __shared__ int s_b;
    int tid = threadIdx.x;

    for (;;) {
        __syncthreads();
        if (tid == 0) s_b = atomicAdd(&g_gemm_next, 1);
        __syncthreads();
        int g = s_b;
        if (g >= GEMM_ITEMS) return;          // uniform per CTA
        int mb = g >> 4;
        int nb = g & 15;

        // help with producer work until this item's inputs are ready
        for (;;) {
            __syncthreads();
            if (tid == 0) {
                bool ready = (atomicAdd(&g_wcount, 0) == W_UNITS) &&
                             (atomicAdd(&g_mb_count[mb], 0) == UNITS_PER_MB);
                s_b = ready ? -1 : atomicAdd(&g_unit_next, 1);
            }
            __syncthreads();
            int u = s_b;
            if (u < 0) break;
            if (u < W_UNITS) {
                do_w_unit(u, W, dyn, tid);
                __syncthreads();
                if (tid == 0) { __threadfence(); atomicAdd(&g_wcount, 1); }
            } else if (u < UNITS_TOTAL) {
                int m = u - W_UNITS;
                do_mean_unit(m, self_vecs, neigh, tid);
                __syncthreads();
                if (tid == 0) {
                    __threadfence();
                    atomicAdd(&g_mb_count[m >> 4], 1);
                }
            } else {
                if (tid == 0) __nanosleep(256);   // all producer work claimed; poll
            }
        }
        __threadfence();                       // order flag read before g_A/g_WT reads
        do_gemm(mb, nb, bias, out, dyn, tid);
    }
}

// ---------------------------------------------------------------------------
// Launch
// ---------------------------------------------------------------------------
extern "C" void kernel_launch(void* const* d_in, const int* in_sizes, int n_in,
                              void* d_out, int out_size)
{
    const float* self_vecs = (const float*)d_in[0];   // [16384, 512]
    const float* neigh     = (const float*)d_in[1];   // [16384, 25, 512]
    // d_in[2] = temperature (unused by reference)
    const float* W         = (const float*)d_in[3];   // [512, 1024]
    const float* b         = (const float*)d_in[4];   // [1024]
    float* out = (float*)d_out;                       // [16384, 1024]

    zero_kernel<<<1, 256>>>();
    fused_kernel<<<GRID_CTAS, 256, SMEM_BYTES>>>(self_vecs, neigh, W, b, out);
}